// round 12
// baseline (speedup 1.0000x reference)
#include <cuda_runtime.h>
#include <math.h>

#define KENC 1184
#define KDEC 880
#define NENC 2560
#define GPART 327680u
#define NB 128

typedef unsigned long long ull;

// ---- scratch offsets (floats) ----
#define OFF_XCE   0u
#define OFF_XCD   151552u
#define OFF_CENC  264192u
#define OFF_CDEC  329728u
#define ZEROSPAN  395264u
#define OFF_G     395264u
#define OFF_LPRE  1705984u
#define OFF_HLANG 5900288u
#define OFF_APRE  6948864u
#define OFF_WENC2 9046016u
#define OFF_WDEC  12077056u
#define OFF_BENC  13879296u
#define OFF_BDEC  13881856u
#define OFF_WHT   13883904u
#define OFF_BLF   14014976u
#define OFF_BLB   14015488u
#define OFF_CENC2 14016000u
#define SCR_TOTAL 14081536u

__device__ float S_g[SCR_TOTAL];
__device__ unsigned g_cnt;
__device__ unsigned g_gen;

__device__ __forceinline__ float sigm(float x) { return 1.f / (1.f + expf(-x)); }
__device__ __forceinline__ ull pk2(float lo, float hi) {
    ull r; asm("mov.b64 %0,{%1,%2};" : "=l"(r) : "f"(lo), "f"(hi)); return r;
}
__device__ __forceinline__ void upk2(ull v, float& lo, float& hi) {
    asm("mov.b64 {%0,%1},%2;" : "=f"(lo), "=f"(hi) : "l"(v));
}
__device__ __forceinline__ ull fma2(ull a, ull b, ull c) {
    ull d; asm("fma.rn.f32x2 %0,%1,%2,%3;" : "=l"(d) : "l"(a), "l"(b), "l"(c)); return d;
}

// ---------- grid barrier ----------
__device__ __forceinline__ void gsync() {
    __syncthreads();
    if (threadIdx.x == 0) {
        __threadfence();
        unsigned gen = *((volatile unsigned*)&g_gen);
        if (atomicAdd(&g_cnt, 1u) == NB - 1u) {
            atomicExch(&g_cnt, 0u);
            __threadfence();
            atomicExch(&g_gen, gen + 1u);
        } else {
            while (*((volatile unsigned*)&g_gen) == gen) { __nanosleep(64); }
        }
        __threadfence();
    }
    __syncthreads();
}

// ---------- shared memory overlays ----------
struct SmemGemm {
    ull  As2[2][16][65];
    float Bs[2][16][132];
};
struct SmemFused {
    float h_s[512];
    float hd_s[512];
    float lg_s[32];
    float w_s[80];
    float p_s[5];
    float F_s[2][5][64];
    float sF_s[10], inv_s[10];
    __align__(16) float Mw_s[960];
    float tmp_s[960];
    float xs_s[64][65];
    __align__(16) ull hq2[1024];
};
union SmemAll { SmemGemm g; SmemFused f; };

// ---------- standalone f32x2 GEMM (prologue) ----------
__global__ __launch_bounds__(256) void gemm2b(const float* __restrict__ X, int ldx,
                                              const float* __restrict__ W, int ldw,
                                              const float* __restrict__ bias,
                                              float* __restrict__ Y, int ldy, int K)
{
    __shared__ ull  As2[2][16][65];
    __shared__ float Bs[2][16][132];
    int tid = threadIdx.x;
    int m0 = blockIdx.y * 64, n0 = blockIdx.x * 128;
    int warp = tid >> 5, lane = tid & 31;
    int w8 = warp * 8;
    ull acc0[8], acc1[8];
#pragma unroll
    for (int i = 0; i < 8; i++) { acc0[i] = 0ull; acc1[i] = 0ull; }
    int ntile = (K + 15) >> 4;
    float ar[4], br[8];
    auto LDGT = [&](int k0) {
#pragma unroll
        for (int it = 0; it < 4; it++) {
            int idx = tid + it * 256;
            int m = idx >> 4, k = idx & 15;
            int gk = k0 + k;
            ar[it] = (gk < K) ? X[(size_t)(m0 + m) * ldx + gk] : 0.f;
        }
#pragma unroll
        for (int it = 0; it < 8; it++) {
            int idx = tid + it * 256;
            int n = idx >> 4, k = idx & 15;
            int gk = k0 + k;
            br[it] = (gk < K) ? W[(size_t)(n0 + n) * ldw + gk] : 0.f;
        }
    };
    auto STST = [&](int buf) {
#pragma unroll
        for (int it = 0; it < 4; it++) {
            int idx = tid + it * 256;
            As2[buf][idx & 15][idx >> 4] = pk2(ar[it], ar[it]);
        }
#pragma unroll
        for (int it = 0; it < 8; it++) {
            int idx = tid + it * 256;
            Bs[buf][idx & 15][idx >> 4] = br[it];
        }
    };
    LDGT(0); STST(0); __syncthreads();
    for (int ti = 0; ti < ntile; ti++) {
        if (ti + 1 < ntile) LDGT((ti + 1) * 16);
        int buf = ti & 1;
#pragma unroll
        for (int kk = 0; kk < 16; kk++) {
            ull b0 = *reinterpret_cast<const ull*>(&Bs[buf][kk][2 * lane]);
            ull b1 = *reinterpret_cast<const ull*>(&Bs[buf][kk][2 * lane + 64]);
#pragma unroll
            for (int i = 0; i < 8; i++) {
                ull a = As2[buf][kk][w8 + i];
                acc0[i] = fma2(a, b0, acc0[i]);
                acc1[i] = fma2(a, b1, acc1[i]);
            }
        }
        __syncthreads();
        if (ti + 1 < ntile) { STST(buf ^ 1); __syncthreads(); }
    }
#pragma unroll
    for (int i = 0; i < 8; i++) {
        int gm = m0 + w8 + i;
        int gn = n0 + 2 * lane;
        float lo, hi;
        upk2(acc0[i], lo, hi);
        lo += bias[gn]; hi += bias[gn + 1];
        *reinterpret_cast<float2*>(&Y[(size_t)gm * ldy + gn]) = make_float2(lo, hi);
        upk2(acc1[i], lo, hi);
        lo += bias[gn + 64]; hi += bias[gn + 65];
        *reinterpret_cast<float2*>(&Y[(size_t)gm * ldy + gn + 64]) = make_float2(lo, hi);
    }
}

// ---------- init ----------
#define N_WENC2 (2560u*1184u)
#define N_WDEC  (2048u*880u)
#define N_WHT   (2u*128u*512u)
#define INIT_TOTAL (ZEROSPAN + N_WENC2 + N_WDEC + 2560u + 2048u + N_WHT + 1024u)

__global__ void k_init(float* __restrict__ S,
                       const float* __restrict__ enc_Wih, const float* __restrict__ enc_Whh,
                       const float* __restrict__ enc_bih, const float* __restrict__ enc_bhh,
                       const float* __restrict__ dec_Wih, const float* __restrict__ dec_Whh,
                       const float* __restrict__ dec_bih, const float* __restrict__ dec_bhh,
                       const float* __restrict__ align_W1,
                       const float* __restrict__ lf_Whh, const float* __restrict__ lb_Whh,
                       const float* __restrict__ lf_bih, const float* __restrict__ lf_bhh,
                       const float* __restrict__ lb_bih, const float* __restrict__ lb_bhh)
{
    for (unsigned i = blockIdx.x * blockDim.x + threadIdx.x; i < INIT_TOTAL;
         i += gridDim.x * blockDim.x) {
        unsigned r = i;
        if (r < ZEROSPAN) { S[r] = 0.f; continue; }
        r -= ZEROSPAN;
        if (r < N_WENC2) {
            unsigned row = r / 1184u, col = r % 1184u;
            float v = 0.f;
            if (row < 2048u) {
                if (col < 662u) v = enc_Wih[row * 662u + col];
                else if (col < 1174u) v = enc_Whh[row * 512u + (col - 662u)];
            } else {
                if (col >= 150u && col < 662u)
                    v = align_W1[(row - 2048u) * 768u + (col - 150u)];
            }
            S[OFF_WENC2 + r] = v; continue;
        }
        r -= N_WENC2;
        if (r < N_WDEC) {
            unsigned row = r / 880u, col = r % 880u;
            float v = 0.f;
            if (col < 356u) v = dec_Wih[row * 356u + col];
            else if (col < 868u) v = dec_Whh[row * 512u + (col - 356u)];
            S[OFF_WDEC + r] = v; continue;
        }
        r -= N_WDEC;
        if (r < 2560u) {
            S[OFF_BENC + r] = (r < 2048u) ? (enc_bih[r] + enc_bhh[r]) : 0.f;
            continue;
        }
        r -= 2560u;
        if (r < 2048u) { S[OFF_BDEC + r] = dec_bih[r] + dec_bhh[r]; continue; }
        r -= 2048u;
        if (r < N_WHT) {
            unsigned dir = r / 65536u, rem = r % 65536u;
            unsigned k = rem / 512u, j = rem % 512u;
            const float* Wsrc = dir ? lb_Whh : lf_Whh;
            S[OFF_WHT + r] = Wsrc[j * 128u + k];
            continue;
        }
        r -= N_WHT;
        if (r < 512u) S[OFF_BLF + r] = lf_bih[r] + lf_bhh[r];
        else S[OFF_BLB + (r - 512u)] = lb_bih[r - 512u] + lb_bhh[r - 512u];
    }
}

// ---------- bi-LSTM: 128 blocks x 512 thr, pair per block, unroll 32 ----------
__global__ __launch_bounds__(512) void k_bilstm_pair(const float* __restrict__ lpre,
                                                     const float* __restrict__ WhhT,
                                                     float* __restrict__ hlang)
{
    int dir = blockIdx.x >> 6;
    int pr = blockIdx.x & 63;
    int b0 = pr * 2;
    int tid = threadIdx.x;
    __shared__ ull h2[128];
    __shared__ float2 c2s[128];
    __shared__ ull g2[512];
    if (tid < 128) { h2[tid] = 0ull; c2s[tid] = make_float2(0.f, 0.f); }
    __syncthreads();
    const float* Wt = WhhT + (size_t)dir * 65536;
    const float* pre = lpre + (size_t)dir * 2097152;
    int j = tid;
    for (int t = 0; t < 32; t++) {
        int tt = dir ? (31 - t) : t;
        float lo = pre[((size_t)b0 * 32 + tt) * 512 + j];
        float hi = pre[((size_t)(b0 + 1) * 32 + tt) * 512 + j];
        ull acc = pk2(lo, hi);
#pragma unroll 32
        for (int k = 0; k < 128; k++) {
            float w = Wt[k * 512 + j];
            acc = fma2(pk2(w, w), h2[k], acc);
        }
        g2[j] = acc;
        __syncthreads();
        if (tid < 128) {
            int u = tid;
            float i0, i1, f0, f1, gg0, gg1, o0, o1;
            upk2(g2[u], i0, i1);
            upk2(g2[128 + u], f0, f1);
            upk2(g2[256 + u], gg0, gg1);
            upk2(g2[384 + u], o0, o1);
            float2 cc = c2s[u];
            float c20 = sigm(f0) * cc.x + sigm(i0) * tanhf(gg0);
            float c21 = sigm(f1) * cc.y + sigm(i1) * tanhf(gg1);
            float hh0 = sigm(o0) * tanhf(c20);
            float hh1 = sigm(o1) * tanhf(c21);
            c2s[u] = make_float2(c20, c21);
            h2[u] = pk2(hh0, hh1);
            hlang[((size_t)b0 * 32 + tt) * 256 + dir * 128 + u] = hh0;
            hlang[((size_t)(b0 + 1) * 32 + tt) * 256 + dir * 128 + u] = hh1;
        }
        __syncthreads();
    }
}

// ---------- shared filterbank ----------
__device__ void filterbank_block(const float* p, float (*F)[5][64], float* sF, float* inv)
{
    int tid = threadIdx.x, lane = tid & 31, warp = tid >> 5;
    float gx = 32.5f * (p[0] + 1.f);
    float gy = 32.5f * (p[1] + 1.f);
    float inv2s2 = 0.5f * expf(-p[2]);
    float delta = 15.75f * expf(p[3]);
    for (int i = tid; i < 640; i += 512) {
        int f = i / 320, rem = i % 320, row = rem / 64, a = rem & 63;
        float mu = (f == 0 ? gx : gy) + ((float)row - 3.f) * delta;
        float d = (float)a - mu;
        F[f][row][a] = expf(-d * d * inv2s2);
    }
    __syncthreads();
    if (warp < 10) {
        int f = warp / 5, row = warp % 5;
        float s = F[f][row][lane] + F[f][row][lane + 32];
#pragma unroll
        for (int o = 16; o; o >>= 1) s += __shfl_xor_sync(0xffffffffu, s, o);
        if (!lane) {
            float iv = 1.f / (s + 1e-8f);
            inv[warp] = iv;
            sF[warp] = s * iv;
        }
    }
    __syncthreads();
    for (int i = tid; i < 640; i += 512) {
        int f = i / 320, rem = i % 320, row = rem / 64, a = rem & 63;
        F[f][row][a] *= inv[f * 5 + row];
    }
    __syncthreads();
}

// ---------- glimpse ----------
__device__ void do_glimpse(int b, const float* __restrict__ x, float (*F)[5][64],
                           const float* sF, float gamma, float* __restrict__ xce,
                           float* tmp_s, float (*xs)[65])
{
    int tid = threadIdx.x, lane = tid & 31, warp = tid >> 5;
    for (int c = 0; c < 3; c++) {
        __syncthreads();
        for (int i = tid; i < 4096; i += 512)
            xs[i >> 6][i & 63] = x[(size_t)b * 12288 + c * 4096 + i];
        __syncthreads();
        if (tid < 320) {
            int yy = tid & 63, j = tid >> 6;
            float s = 0.f;
#pragma unroll 8
            for (int xx = 0; xx < 64; xx++) s += xs[yy][xx] * F[0][j][xx];
            tmp_s[(c * 5 + j) * 64 + yy] = s;
        }
    }
    __syncthreads();
    for (int o = warp; o < 75; o += 16) {
        int j = o % 5, i5 = (o / 5) % 5, c = o / 25;
        const float* tp = tmp_s + (c * 5 + j) * 64;
        float s = F[1][i5][lane] * tp[lane] + F[1][i5][lane + 32] * tp[lane + 32];
#pragma unroll
        for (int off = 16; off; off >>= 1) s += __shfl_xor_sync(0xffffffffu, s, off);
        if (!lane) {
            xce[(size_t)b * KENC + o] = s * gamma;
            xce[(size_t)b * KENC + 75 + o] = (s - 0.5f * sF[5 + i5] * sF[j]) * gamma;
        }
    }
}

// ---------- glimpse t=0 ----------
__global__ __launch_bounds__(512) void k_glimpse0(float* __restrict__ xce,
                                                  const float* __restrict__ x,
                                                  const float* __restrict__ attn_b)
{
    int b = blockIdx.x;
    int tid = threadIdx.x;
    __shared__ float p_s[5];
    __shared__ float F_s[2][5][64];
    __shared__ float sF_s[10], inv_s[10];
    __shared__ float tmp_s[960];
    __shared__ float xs_s[64][65];
    if (tid < 5) p_s[tid] = attn_b[tid];
    __syncthreads();
    float gamma = expf(p_s[4]);
    filterbank_block(p_s, F_s, sF_s, inv_s);
    do_glimpse(b, x, F_s, sF_s, gamma, xce, tmp_s, xs_s);
}

// ---------- in-megakernel GEMM phase ----------
__device__ void gemm_phase512(SmemGemm& sm,
                              const float* __restrict__ X, int ldx,
                              const float* __restrict__ W, int ldw,
                              float* __restrict__ Yp, int ldy,
                              int m0, int n0, int kbeg, int kend)
{
    int tid = threadIdx.x;
    int warp = tid >> 5, lane = tid & 31;
    int w4 = warp * 4;
    ull acc0[4] = {0ull, 0ull, 0ull, 0ull};
    ull acc1[4] = {0ull, 0ull, 0ull, 0ull};
    int ntile = (kend - kbeg + 15) >> 4;
    float ar[2], br[4];
    auto LDGT = [&](int k0) {
#pragma unroll
        for (int it = 0; it < 2; it++) {
            int idx = tid + it * 512;
            int m = idx >> 4, k = idx & 15;
            int gk = k0 + k;
            ar[it] = (gk < kend) ? X[(size_t)(m0 + m) * ldx + gk] : 0.f;
        }
#pragma unroll
        for (int it = 0; it < 4; it++) {
            int idx = tid + it * 512;
            int n = idx >> 4, k = idx & 15;
            int gk = k0 + k;
            br[it] = (gk < kend) ? W[(size_t)(n0 + n) * ldw + gk] : 0.f;
        }
    };
    auto STST = [&](int buf) {
#pragma unroll
        for (int it = 0; it < 2; it++) {
            int idx = tid + it * 512;
            sm.As2[buf][idx & 15][idx >> 4] = pk2(ar[it], ar[it]);
        }
#pragma unroll
        for (int it = 0; it < 4; it++) {
            int idx = tid + it * 512;
            sm.Bs[buf][idx & 15][idx >> 4] = br[it];
        }
    };
    LDGT(kbeg); STST(0); __syncthreads();
    for (int ti = 0; ti < ntile; ti++) {
        if (ti + 1 < ntile) LDGT(kbeg + (ti + 1) * 16);
        int buf = ti & 1;
#pragma unroll
        for (int kk = 0; kk < 16; kk++) {
            ull b0 = *reinterpret_cast<const ull*>(&sm.Bs[buf][kk][2 * lane]);
            ull b1 = *reinterpret_cast<const ull*>(&sm.Bs[buf][kk][2 * lane + 64]);
#pragma unroll
            for (int i = 0; i < 4; i++) {
                ull a = sm.As2[buf][kk][w4 + i];
                acc0[i] = fma2(a, b0, acc0[i]);
                acc1[i] = fma2(a, b1, acc1[i]);
            }
        }
        __syncthreads();
        if (ti + 1 < ntile) { STST(buf ^ 1); __syncthreads(); }
    }
#pragma unroll
    for (int i = 0; i < 4; i++) {
        int gm = m0 + w4 + i;
        int gn = n0 + 2 * lane;
        float lo, hi;
        upk2(acc0[i], lo, hi);
        *reinterpret_cast<float2*>(&Yp[(size_t)gm * ldy + gn]) = make_float2(lo, hi);
        upk2(acc1[i], lo, hi);
        *reinterpret_cast<float2*>(&Yp[(size_t)gm * ldy + gn + 64]) = make_float2(lo, hi);
    }
}

// ---------- enc owner phase: pointwise + align + sent for one batch ----------
__device__ void enc_own(SmemFused& sf, int b, const float* __restrict__ G,
                        const float* __restrict__ cencR, float* __restrict__ cencW,
                        float* __restrict__ xce, float* __restrict__ xcd,
                        const float* __restrict__ benc,
                        const float* __restrict__ apre, const float* __restrict__ w2,
                        const float* __restrict__ hlang)
{
    int tid = threadIdx.x, lane = tid & 31, warp = tid >> 5;
    const float* g0 = G + (size_t)b * NENC;
    {
        int u = tid;
        float gi = benc[u], gf = benc[512 + u], gg = benc[1024 + u], go = benc[1536 + u];
        float hp = 0.f;
#pragma unroll
        for (int z = 0; z < 3; z++) {
            const float* gz = g0 + (size_t)z * GPART;
            gi += gz[u]; gf += gz[512 + u]; gg += gz[1024 + u]; go += gz[1536 + u];
            hp += gz[2048 + u];
        }
        float c2 = sigm(gf) * cencR[b * 512 + u] + sigm(gi) * tanhf(gg);
        float h = sigm(go) * tanhf(c2);
        cencW[b * 512 + u] = c2;
        xce[(size_t)b * KENC + 662 + u] = h;
        sf.hd_s[u] = hp;
    }
    __syncthreads();
    for (int t = warp; t < 32; t += 16) {
        const float* ap = apre + ((size_t)b * 32 + t) * 512;
        float s = 0.f;
        for (int al = lane; al < 512; al += 32)
            s += tanhf(ap[al] + sf.hd_s[al]) * w2[al];
#pragma unroll
        for (int o = 16; o; o >>= 1) s += __shfl_xor_sync(0xffffffffu, s, o);
        if (!lane) sf.lg_s[t] = s;
    }
    __syncthreads();
    if (warp == 0) {
        float v = sf.lg_s[lane];
        float m = v;
#pragma unroll
        for (int o = 16; o; o >>= 1) m = fmaxf(m, __shfl_xor_sync(0xffffffffu, m, o));
        float e = expf(v - m);
        float s = e;
#pragma unroll
        for (int o = 16; o; o >>= 1) s += __shfl_xor_sync(0xffffffffu, s, o);
        sf.lg_s[lane] = e / s;
    }
    __syncthreads();
    if (tid < 256) {
        int jj = tid;
        float s = 0.f;
        const float* hl = hlang + (size_t)b * 8192 + jj;
#pragma unroll 8
        for (int t = 0; t < 32; t++) s += sf.lg_s[t] * hl[t * 256];
        xcd[(size_t)b * KDEC + 100 + jj] = s;
    }
    __syncthreads();
}

// ---------- enc q-block phase: 4-batch batched mu/sig GEMV -> q ----------
__device__ void enc_q(SmemFused& sf, int b0, const float* __restrict__ G,
                      const float* __restrict__ cencR, const float* __restrict__ benc,
                      const float* __restrict__ mu_W, const float* __restrict__ mu_b,
                      const float* __restrict__ sig_W, const float* __restrict__ sig_b,
                      const float* __restrict__ eps_t, float* __restrict__ xcd)
{
    int tid = threadIdx.x, lane = tid & 31, warp = tid >> 5;
    // self-compute h_enc2 for 4 batches (no writes to shared state)
    {
        int u = tid;
        float bi = benc[u], bf = benc[512 + u], bg = benc[1024 + u], bo = benc[1536 + u];
#pragma unroll
        for (int p2 = 0; p2 < 2; p2++) {
            float hv[2];
#pragma unroll
            for (int q = 0; q < 2; q++) {
                int b = b0 + 2 * p2 + q;
                const float* g0 = G + (size_t)b * NENC;
                float gi = bi, gf = bf, gg = bg, go = bo;
#pragma unroll
                for (int z = 0; z < 3; z++) {
                    const float* gz = g0 + (size_t)z * GPART;
                    gi += gz[u]; gf += gz[512 + u]; gg += gz[1024 + u]; go += gz[1536 + u];
                }
                float c2 = sigm(gf) * cencR[b * 512 + u] + sigm(gi) * tanhf(gg);
                hv[q] = sigm(go) * tanhf(c2);
            }
            sf.hq2[p2 * 512 + u] = pk2(hv[0], hv[1]);
        }
    }
    __syncthreads();
    for (int o = warp; o < 100; o += 16) {
        const float* mr = mu_W + o * 512;
        const float* sr = sig_W + o * 512;
        ull am[2] = {0ull, 0ull}, as[2] = {0ull, 0ull};
        for (int k = lane; k < 512; k += 32) {
            float wm = mr[k], ws = sr[k];
            ull wm2 = pk2(wm, wm), ws2 = pk2(ws, ws);
            ull h0 = sf.hq2[k], h1 = sf.hq2[512 + k];
            am[0] = fma2(wm2, h0, am[0]);
            am[1] = fma2(wm2, h1, am[1]);
            as[0] = fma2(ws2, h0, as[0]);
            as[1] = fma2(ws2, h1, as[1]);
        }
        float m0, m1, m2, m3, s0, s1, s2, s3;
        upk2(am[0], m0, m1); upk2(am[1], m2, m3);
        upk2(as[0], s0, s1); upk2(as[1], s2, s3);
#pragma unroll
        for (int off = 16; off; off >>= 1) {
            m0 += __shfl_xor_sync(0xffffffffu, m0, off);
            m1 += __shfl_xor_sync(0xffffffffu, m1, off);
            m2 += __shfl_xor_sync(0xffffffffu, m2, off);
            m3 += __shfl_xor_sync(0xffffffffu, m3, off);
            s0 += __shfl_xor_sync(0xffffffffu, s0, off);
            s1 += __shfl_xor_sync(0xffffffffu, s1, off);
            s2 += __shfl_xor_sync(0xffffffffu, s2, off);
            s3 += __shfl_xor_sync(0xffffffffu, s3, off);
        }
        if (!lane) {
            float mb = mu_b[o], sb = sig_b[o];
            xcd[(size_t)(b0 + 0) * KDEC + o] = (m0 + mb) + eps_t[(b0 + 0) * 100 + o] * expf(s0 + sb);
            xcd[(size_t)(b0 + 1) * KDEC + o] = (m1 + mb) + eps_t[(b0 + 1) * 100 + o] * expf(s1 + sb);
            xcd[(size_t)(b0 + 2) * KDEC + o] = (m2 + mb) + eps_t[(b0 + 2) * 100 + o] * expf(s2 + sb);
            xcd[(size_t)(b0 + 3) * KDEC + o] = (m3 + mb) + eps_t[(b0 + 3) * 100 + o] * expf(s3 + sb);
        }
    }
    __syncthreads();
}

// ---------- dec fused phase ----------
__device__ void dec_phase(SmemFused& sf, int b, const float* __restrict__ G,
                          float* __restrict__ cdec, float* __restrict__ xce,
                          float* __restrict__ xcd, const float* __restrict__ x,
                          const float* __restrict__ bdec,
                          const float* __restrict__ write_W, const float* __restrict__ write_b,
                          const float* __restrict__ attn_W, const float* __restrict__ attn_b,
                          float* __restrict__ out_t, int doGlimpse)
{
    int tid = threadIdx.x, lane = tid & 31, warp = tid >> 5;
    const float* g0 = G + (size_t)b * 2048;
    {
        int u = tid;
        float gi = bdec[u], gf = bdec[512 + u], gg = bdec[1024 + u], go = bdec[1536 + u];
#pragma unroll
        for (int z = 0; z < 4; z++) {
            const float* gz = g0 + (size_t)z * GPART;
            gi += gz[u]; gf += gz[512 + u]; gg += gz[1024 + u]; go += gz[1536 + u];
        }
        float c2 = sigm(gf) * cdec[b * 512 + u] + sigm(gi) * tanhf(gg);
        float h = sigm(go) * tanhf(c2);
        cdec[b * 512 + u] = c2;
        xce[(size_t)b * KENC + 150 + u] = h;
        xcd[(size_t)b * KDEC + 356 + u] = h;
        sf.h_s[u] = h;
    }
    __syncthreads();
    for (int o = warp; o < 80; o += 16) {
        const float* row = (o < 75) ? (write_W + o * 512) : (attn_W + (o - 75) * 512);
        float s = 0.f;
        for (int k = lane; k < 512; k += 32) s += row[k] * sf.h_s[k];
#pragma unroll
        for (int off = 16; off; off >>= 1) s += __shfl_xor_sync(0xffffffffu, s, off);
        if (!lane) {
            if (o < 75) sf.w_s[o] = s + write_b[o];
            else sf.p_s[o - 75] = s + attn_b[o - 75];
        }
    }
    __syncthreads();
    float gamma = expf(sf.p_s[4]);
    float ginv = expf(-sf.p_s[4]);
    filterbank_block(sf.p_s, sf.F_s, sf.sF_s, sf.inv_s);
    for (int idx = tid; idx < 960; idx += 512) {
        int xx = idx & 63, rest = idx >> 6;
        int i5 = rest % 5, c = rest / 5;
        float s = 0.f;
#pragma unroll
        for (int jj = 0; jj < 5; jj++) s += sf.w_s[c * 25 + i5 * 5 + jj] * sf.F_s[0][jj][xx];
        sf.Mw_s[idx] = s;
    }
    __syncthreads();
    // float4 output: out[b,c,y,x]
    for (int idx4 = tid; idx4 < 3072; idx4 += 512) {
        int xg = (idx4 & 15) * 4;
        int yy = (idx4 >> 4) & 63;
        int c = idx4 >> 10;
        float4 s = make_float4(0.f, 0.f, 0.f, 0.f);
#pragma unroll
        for (int i = 0; i < 5; i++) {
            float f = sf.F_s[1][i][yy];
            const float4 m4 = *reinterpret_cast<const float4*>(&sf.Mw_s[(c * 5 + i) * 64 + xg]);
            s.x += f * m4.x; s.y += f * m4.y; s.z += f * m4.z; s.w += f * m4.w;
        }
        s.x *= ginv; s.y *= ginv; s.z *= ginv; s.w *= ginv;
        *reinterpret_cast<float4*>(&out_t[(size_t)b * 12288 + idx4 * 4]) = s;
    }
    if (doGlimpse)
        do_glimpse(b, x, sf.F_s, sf.sF_s, gamma, xce, sf.tmp_s, sf.xs_s);
}

// ---------- persistent scan megakernel ----------
__global__ __launch_bounds__(512) void k_scan(float* __restrict__ S,
                                              const float* __restrict__ x,
                                              const float* __restrict__ eps_q,
                                              const float* __restrict__ mu_W,
                                              const float* __restrict__ mu_b,
                                              const float* __restrict__ sig_W,
                                              const float* __restrict__ sig_b,
                                              const float* __restrict__ write_W,
                                              const float* __restrict__ write_b,
                                              const float* __restrict__ attn_W,
                                              const float* __restrict__ attn_b,
                                              const float* __restrict__ w2,
                                              float* __restrict__ out)
{
    __shared__ __align__(16) SmemAll sm;
    SmemGemm& sg = sm.g;
    SmemFused& sf = sm.f;
    int blk = blockIdx.x;
    float* xce = S + OFF_XCE;
    float* xcd = S + OFF_XCD;
    float* G   = S + OFF_G;

    for (int t = 0; t < 32; t++) {
        const float* cencR = S + ((t & 1) ? OFF_CENC2 : OFF_CENC);
        float* cencW = S + ((t & 1) ? OFF_CENC : OFF_CENC2);
        // --- P1: enc GEMM, 120 units ---
        if (blk < 120) {
            int z = blk / 40, rem = blk % 40;
            int my = rem / 20, nx = rem % 20;
            int kbeg = z * 400, kend = min(KENC, kbeg + 400);
            gemm_phase512(sg, xce, KENC, S + OFF_WENC2, KENC,
                          G + (size_t)z * GPART, NENC,
                          my * 64, nx * 128, kbeg, kend);
        }
        gsync();
        // --- P2: merged enc pointwise + align/sent (96 owners) || mu/sig q (32 blocks) ---
        if (blk < 96) {
            enc_own(sf, blk, G, cencR, cencW, xce, xcd, S + OFF_BENC,
                    S + OFF_APRE, w2, S + OFF_HLANG);
            if (blk < 32)
                enc_own(sf, 96 + blk, G, cencR, cencW, xce, xcd, S + OFF_BENC,
                        S + OFF_APRE, w2, S + OFF_HLANG);
        } else {
            enc_q(sf, (blk - 96) * 4, G, cencR, S + OFF_BENC,
                  mu_W, mu_b, sig_W, sig_b,
                  eps_q + (size_t)t * 12800, xcd);
        }
        gsync();
        // --- P3: dec GEMM, 128 units ---
        {
            int z = blk >> 5, rem = blk & 31;
            int my = rem >> 4, nx = rem & 15;
            int kbeg = z * 224, kend = min(KDEC, kbeg + 224);
            gemm_phase512(sg, xcd, KDEC, S + OFF_WDEC, KDEC,
                          G + (size_t)z * GPART, 2048,
                          my * 64, nx * 128, kbeg, kend);
        }
        gsync();
        // --- P4: dec fused + output + next glimpse ---
        dec_phase(sf, blk, G, S + OFF_CDEC, xce, xcd, x, S + OFF_BDEC,
                  write_W, write_b, attn_W, attn_b,
                  out + (size_t)t * 1572864u, (t < 31) ? 1 : 0);
        if (t < 31) gsync();
    }
}

// ---------- host ----------
extern "C" void kernel_launch(void* const* d_in, const int* in_sizes, int n_in,
                              void* d_out, int out_size)
{
    const float* x       = (const float*)d_in[0];
    const float* y       = (const float*)d_in[1];
    const float* eps_q   = (const float*)d_in[2];
    const float* enc_Wih = (const float*)d_in[3];
    const float* enc_Whh = (const float*)d_in[4];
    const float* enc_bih = (const float*)d_in[5];
    const float* enc_bhh = (const float*)d_in[6];
    const float* dec_Wih = (const float*)d_in[7];
    const float* dec_Whh = (const float*)d_in[8];
    const float* dec_bih = (const float*)d_in[9];
    const float* dec_bhh = (const float*)d_in[10];
    const float* mu_W    = (const float*)d_in[11];
    const float* mu_b    = (const float*)d_in[12];
    const float* sig_W   = (const float*)d_in[13];
    const float* sig_b   = (const float*)d_in[14];
    const float* write_W = (const float*)d_in[15];
    const float* write_b = (const float*)d_in[16];
    const float* align_W1= (const float*)d_in[17];
    const float* align_b1= (const float*)d_in[18];
    const float* align_w2= (const float*)d_in[19];
    const float* attn_W  = (const float*)d_in[20];
    const float* attn_b  = (const float*)d_in[21];
    const float* lf_Wih  = (const float*)d_in[22];
    const float* lf_Whh  = (const float*)d_in[23];
    const float* lf_bih  = (const float*)d_in[24];
    const float* lf_bhh  = (const float*)d_in[25];
    const float* lb_Wih  = (const float*)d_in[26];
    const float* lb_Whh  = (const float*)d_in[27];
    const float* lb_bih  = (const float*)d_in[28];
    const float* lb_bhh  = (const float*)d_in[29];
    float* out = (float*)d_out;

    float* S;
    cudaGetSymbolAddress((void**)&S, S_g);

    k_init<<<4096, 256>>>(S, enc_Wih, enc_Whh, enc_bih, enc_bhh,
                          dec_Wih, dec_Whh, dec_bih, dec_bhh,
                          align_W1, lf_Whh, lb_Whh,
                          lf_bih, lf_bhh, lb_bih, lb_bhh);

    gemm2b<<<dim3(4, 64), 256>>>(y, 300, lf_Wih, 300, S + OFF_BLF,
                                 S + OFF_LPRE, 512, 300);
    gemm2b<<<dim3(4, 64), 256>>>(y, 300, lb_Wih, 300, S + OFF_BLB,
                                 S + OFF_LPRE + 2097152u, 512, 300);

    k_bilstm_pair<<<128, 512>>>(S + OFF_LPRE, S + OFF_WHT, S + OFF_HLANG);

    gemm2b<<<dim3(4, 64), 256>>>(S + OFF_HLANG, 256, align_W1 + 512, 768,
                                 align_b1, S + OFF_APRE, 512, 256);

    k_glimpse0<<<128, 512>>>(S + OFF_XCE, x, attn_b);

    k_scan<<<NB, 512>>>(S, x, eps_q, mu_W, mu_b, sig_W, sig_b,
                        write_W, write_b, attn_W, attn_b, align_w2, out);
}

// round 14
// speedup vs baseline: 1.0721x; 1.0721x over previous
#include <cuda_runtime.h>
#include <math.h>

#define KENC 1184
#define KDEC 880
#define NENC 2560
#define GPART 327680u
#define NB 128
#define WROWS 96

typedef unsigned long long ull;

// ---- scratch offsets (floats) ----
#define OFF_XCE   0u
#define OFF_XCD   151552u
#define OFF_CENC  264192u
#define OFF_CDEC  329728u
#define ZEROSPAN  395264u
#define OFF_G     395264u
#define OFF_LPRE  1705984u
#define OFF_HLANG 5900288u
#define OFF_APRE  6948864u
#define OFF_WENC2 9046016u
#define OFF_WDEC  12077056u
#define OFF_BENC  13879296u
#define OFF_BDEC  13881856u
#define OFF_WHT   13883904u
#define OFF_BLF   14014976u
#define OFF_BLB   14015488u
#define SCR_TOTAL 14016000u

__device__ float S_g[SCR_TOTAL];
__device__ unsigned g_cnt;
__device__ unsigned g_gen;

__device__ __forceinline__ float sigm(float x) { return 1.f / (1.f + expf(-x)); }
__device__ __forceinline__ ull pk2(float lo, float hi) {
    ull r; asm("mov.b64 %0,{%1,%2};" : "=l"(r) : "f"(lo), "f"(hi)); return r;
}
__device__ __forceinline__ void upk2(ull v, float& lo, float& hi) {
    asm("mov.b64 {%0,%1},%2;" : "=f"(lo), "=f"(hi) : "l"(v));
}
__device__ __forceinline__ ull fma2(ull a, ull b, ull c) {
    ull d; asm("fma.rn.f32x2 %0,%1,%2,%3;" : "=l"(d) : "l"(a), "l"(b), "l"(c)); return d;
}

// ---------- grid barrier ----------
__device__ __forceinline__ void gsync() {
    __syncthreads();
    if (threadIdx.x == 0) {
        __threadfence();
        unsigned gen = *((volatile unsigned*)&g_gen);
        if (atomicAdd(&g_cnt, 1u) == NB - 1u) {
            atomicExch(&g_cnt, 0u);
            __threadfence();
            atomicExch(&g_gen, gen + 1u);
        } else {
            while (*((volatile unsigned*)&g_gen) == gen) { __nanosleep(64); }
        }
        __threadfence();
    }
    __syncthreads();
}

// ---------- shared memory overlays ----------
struct SmemGemm {
    ull  As2[2][16][65];
    float Bs[2][16][132];
};
struct SmemFused {
    float h_s[512];
    float hd_s[512];
    float lg_s[32];
    float w_s[80];
    float p_s[5];
    float F_s[2][5][64];
    float sF_s[10], inv_s[10];
    __align__(16) float Mw_s[960];
    float tmp_s[960];
    float xs_s[64][65];
};
union SmemAll { SmemGemm g; SmemFused f; };

// ---------- standalone f32x2 GEMM (prologue) ----------
__global__ __launch_bounds__(256) void gemm2b(const float* __restrict__ X, int ldx,
                                              const float* __restrict__ W, int ldw,
                                              const float* __restrict__ bias,
                                              float* __restrict__ Y, int ldy, int K)
{
    __shared__ ull  As2[2][16][65];
    __shared__ float Bs[2][16][132];
    int tid = threadIdx.x;
    int m0 = blockIdx.y * 64, n0 = blockIdx.x * 128;
    int warp = tid >> 5, lane = tid & 31;
    int w8 = warp * 8;
    ull acc0[8], acc1[8];
#pragma unroll
    for (int i = 0; i < 8; i++) { acc0[i] = 0ull; acc1[i] = 0ull; }
    int ntile = (K + 15) >> 4;
    float ar[4], br[8];
    auto LDGT = [&](int k0) {
#pragma unroll
        for (int it = 0; it < 4; it++) {
            int idx = tid + it * 256;
            int m = idx >> 4, k = idx & 15;
            int gk = k0 + k;
            ar[it] = (gk < K) ? X[(size_t)(m0 + m) * ldx + gk] : 0.f;
        }
#pragma unroll
        for (int it = 0; it < 8; it++) {
            int idx = tid + it * 256;
            int n = idx >> 4, k = idx & 15;
            int gk = k0 + k;
            br[it] = (gk < K) ? W[(size_t)(n0 + n) * ldw + gk] : 0.f;
        }
    };
    auto STST = [&](int buf) {
#pragma unroll
        for (int it = 0; it < 4; it++) {
            int idx = tid + it * 256;
            As2[buf][idx & 15][idx >> 4] = pk2(ar[it], ar[it]);
        }
#pragma unroll
        for (int it = 0; it < 8; it++) {
            int idx = tid + it * 256;
            Bs[buf][idx & 15][idx >> 4] = br[it];
        }
    };
    LDGT(0); STST(0); __syncthreads();
    for (int ti = 0; ti < ntile; ti++) {
        if (ti + 1 < ntile) LDGT((ti + 1) * 16);
        int buf = ti & 1;
#pragma unroll
        for (int kk = 0; kk < 16; kk++) {
            ull b0 = *reinterpret_cast<const ull*>(&Bs[buf][kk][2 * lane]);
            ull b1 = *reinterpret_cast<const ull*>(&Bs[buf][kk][2 * lane + 64]);
#pragma unroll
            for (int i = 0; i < 8; i++) {
                ull a = As2[buf][kk][w8 + i];
                acc0[i] = fma2(a, b0, acc0[i]);
                acc1[i] = fma2(a, b1, acc1[i]);
            }
        }
        __syncthreads();
        if (ti + 1 < ntile) { STST(buf ^ 1); __syncthreads(); }
    }
#pragma unroll
    for (int i = 0; i < 8; i++) {
        int gm = m0 + w8 + i;
        int gn = n0 + 2 * lane;
        float lo, hi;
        upk2(acc0[i], lo, hi);
        lo += bias[gn]; hi += bias[gn + 1];
        *reinterpret_cast<float2*>(&Y[(size_t)gm * ldy + gn]) = make_float2(lo, hi);
        upk2(acc1[i], lo, hi);
        lo += bias[gn + 64]; hi += bias[gn + 65];
        *reinterpret_cast<float2*>(&Y[(size_t)gm * ldy + gn + 64]) = make_float2(lo, hi);
    }
}

// ---------- init ----------
#define N_WENC2 (2560u*1184u)
#define N_WDEC  (2048u*880u)
#define N_WHT   (2u*128u*512u)
#define INIT_TOTAL (ZEROSPAN + N_WENC2 + N_WDEC + 2560u + 2048u + N_WHT + 1024u)

__global__ void k_init(float* __restrict__ S,
                       const float* __restrict__ enc_Wih, const float* __restrict__ enc_Whh,
                       const float* __restrict__ enc_bih, const float* __restrict__ enc_bhh,
                       const float* __restrict__ dec_Wih, const float* __restrict__ dec_Whh,
                       const float* __restrict__ dec_bih, const float* __restrict__ dec_bhh,
                       const float* __restrict__ align_W1,
                       const float* __restrict__ lf_Whh, const float* __restrict__ lb_Whh,
                       const float* __restrict__ lf_bih, const float* __restrict__ lf_bhh,
                       const float* __restrict__ lb_bih, const float* __restrict__ lb_bhh)
{
    for (unsigned i = blockIdx.x * blockDim.x + threadIdx.x; i < INIT_TOTAL;
         i += gridDim.x * blockDim.x) {
        unsigned r = i;
        if (r < ZEROSPAN) { S[r] = 0.f; continue; }
        r -= ZEROSPAN;
        if (r < N_WENC2) {
            unsigned row = r / 1184u, col = r % 1184u;
            float v = 0.f;
            if (row < 2048u) {
                if (col < 662u) v = enc_Wih[row * 662u + col];
                else if (col < 1174u) v = enc_Whh[row * 512u + (col - 662u)];
            } else {
                if (col >= 150u && col < 662u)
                    v = align_W1[(row - 2048u) * 768u + (col - 150u)];
            }
            S[OFF_WENC2 + r] = v; continue;
        }
        r -= N_WENC2;
        if (r < N_WDEC) {
            unsigned row = r / 880u, col = r % 880u;
            float v = 0.f;
            if (col < 356u) v = dec_Wih[row * 356u + col];
            else if (col < 868u) v = dec_Whh[row * 512u + (col - 356u)];
            S[OFF_WDEC + r] = v; continue;
        }
        r -= N_WDEC;
        if (r < 2560u) {
            S[OFF_BENC + r] = (r < 2048u) ? (enc_bih[r] + enc_bhh[r]) : 0.f;
            continue;
        }
        r -= 2560u;
        if (r < 2048u) { S[OFF_BDEC + r] = dec_bih[r] + dec_bhh[r]; continue; }
        r -= 2048u;
        if (r < N_WHT) {
            unsigned dir = r / 65536u, rem = r % 65536u;
            unsigned k = rem / 512u, j = rem % 512u;
            const float* Wsrc = dir ? lb_Whh : lf_Whh;
            S[OFF_WHT + r] = Wsrc[j * 128u + k];
            continue;
        }
        r -= N_WHT;
        if (r < 512u) S[OFF_BLF + r] = lf_bih[r] + lf_bhh[r];
        else S[OFF_BLB + (r - 512u)] = lb_bih[r - 512u] + lb_bhh[r - 512u];
    }
}

// ---------- bi-LSTM: 128 blocks x 512 thr, pair per block, W mostly in smem ----------
__global__ __launch_bounds__(512) void k_bilstm_smem(const float* __restrict__ lpre,
                                                     const float* __restrict__ WhhT,
                                                     float* __restrict__ hlang)
{
    extern __shared__ float dyn[];
    float* Wsm = dyn;                                   // [WROWS][512]
    ull* h2 = (ull*)(dyn + WROWS * 512);                // 128
    float2* c2s = (float2*)(h2 + 128);                  // 128
    ull* g2 = (ull*)(c2s + 128);                        // 512
    int dir = blockIdx.x >> 6;
    int pr = blockIdx.x & 63;
    int b0 = pr * 2;
    int tid = threadIdx.x;
    const float* Wt = WhhT + (size_t)dir * 65536;
    const float* pre = lpre + (size_t)dir * 2097152;
    for (int i = tid; i < WROWS * 512; i += 512) Wsm[i] = Wt[i];
    if (tid < 128) { h2[tid] = 0ull; c2s[tid] = make_float2(0.f, 0.f); }
    __syncthreads();
    int j = tid;
    for (int t = 0; t < 32; t++) {
        int tt = dir ? (31 - t) : t;
        float lo = pre[((size_t)b0 * 32 + tt) * 512 + j];
        float hi = pre[((size_t)(b0 + 1) * 32 + tt) * 512 + j];
        ull acc = pk2(lo, hi);
#pragma unroll 32
        for (int k = 0; k < WROWS; k++) {
            float w = Wsm[k * 512 + j];
            acc = fma2(pk2(w, w), h2[k], acc);
        }
#pragma unroll 32
        for (int k = WROWS; k < 128; k++) {
            float w = Wt[k * 512 + j];
            acc = fma2(pk2(w, w), h2[k], acc);
        }
        g2[j] = acc;
        __syncthreads();
        if (tid < 128) {
            int u = tid;
            float i0, i1, f0, f1, gg0, gg1, o0, o1;
            upk2(g2[u], i0, i1);
            upk2(g2[128 + u], f0, f1);
            upk2(g2[256 + u], gg0, gg1);
            upk2(g2[384 + u], o0, o1);
            float2 cc = c2s[u];
            float c20 = sigm(f0) * cc.x + sigm(i0) * tanhf(gg0);
            float c21 = sigm(f1) * cc.y + sigm(i1) * tanhf(gg1);
            float hh0 = sigm(o0) * tanhf(c20);
            float hh1 = sigm(o1) * tanhf(c21);
            c2s[u] = make_float2(c20, c21);
            h2[u] = pk2(hh0, hh1);
            hlang[((size_t)b0 * 32 + tt) * 256 + dir * 128 + u] = hh0;
            hlang[((size_t)(b0 + 1) * 32 + tt) * 256 + dir * 128 + u] = hh1;
        }
        __syncthreads();
    }
}
#define BILSTM_SMEM (WROWS*512*4 + 128*8 + 128*8 + 512*8)

// ---------- shared filterbank ----------
__device__ void filterbank_block(const float* p, float (*F)[5][64], float* sF, float* inv)
{
    int tid = threadIdx.x, lane = tid & 31, warp = tid >> 5;
    float gx = 32.5f * (p[0] + 1.f);
    float gy = 32.5f * (p[1] + 1.f);
    float inv2s2 = 0.5f * expf(-p[2]);
    float delta = 15.75f * expf(p[3]);
    for (int i = tid; i < 640; i += 512) {
        int f = i / 320, rem = i % 320, row = rem / 64, a = rem & 63;
        float mu = (f == 0 ? gx : gy) + ((float)row - 3.f) * delta;
        float d = (float)a - mu;
        F[f][row][a] = expf(-d * d * inv2s2);
    }
    __syncthreads();
    if (warp < 10) {
        int f = warp / 5, row = warp % 5;
        float s = F[f][row][lane] + F[f][row][lane + 32];
#pragma unroll
        for (int o = 16; o; o >>= 1) s += __shfl_xor_sync(0xffffffffu, s, o);
        if (!lane) {
            float iv = 1.f / (s + 1e-8f);
            inv[warp] = iv;
            sF[warp] = s * iv;
        }
    }
    __syncthreads();
    for (int i = tid; i < 640; i += 512) {
        int f = i / 320, rem = i % 320, row = rem / 64, a = rem & 63;
        F[f][row][a] *= inv[f * 5 + row];
    }
    __syncthreads();
}

// ---------- glimpse ----------
__device__ void do_glimpse(int b, const float* __restrict__ x, float (*F)[5][64],
                           const float* sF, float gamma, float* __restrict__ xce,
                           float* tmp_s, float (*xs)[65])
{
    int tid = threadIdx.x, lane = tid & 31, warp = tid >> 5;
    for (int c = 0; c < 3; c++) {
        __syncthreads();
        for (int i = tid; i < 4096; i += 512)
            xs[i >> 6][i & 63] = x[(size_t)b * 12288 + c * 4096 + i];
        __syncthreads();
        if (tid < 320) {
            int yy = tid & 63, j = tid >> 6;
            float s = 0.f;
#pragma unroll 8
            for (int xx = 0; xx < 64; xx++) s += xs[yy][xx] * F[0][j][xx];
            tmp_s[(c * 5 + j) * 64 + yy] = s;
        }
    }
    __syncthreads();
    for (int o = warp; o < 75; o += 16) {
        int j = o % 5, i5 = (o / 5) % 5, c = o / 25;
        const float* tp = tmp_s + (c * 5 + j) * 64;
        float s = F[1][i5][lane] * tp[lane] + F[1][i5][lane + 32] * tp[lane + 32];
#pragma unroll
        for (int off = 16; off; off >>= 1) s += __shfl_xor_sync(0xffffffffu, s, off);
        if (!lane) {
            xce[(size_t)b * KENC + o] = s * gamma;
            xce[(size_t)b * KENC + 75 + o] = (s - 0.5f * sF[5 + i5] * sF[j]) * gamma;
        }
    }
}

// ---------- glimpse t=0 ----------
__global__ __launch_bounds__(512) void k_glimpse0(float* __restrict__ xce,
                                                  const float* __restrict__ x,
                                                  const float* __restrict__ attn_b)
{
    int b = blockIdx.x;
    int tid = threadIdx.x;
    __shared__ float p_s[5];
    __shared__ float F_s[2][5][64];
    __shared__ float sF_s[10], inv_s[10];
    __shared__ float tmp_s[960];
    __shared__ float xs_s[64][65];
    if (tid < 5) p_s[tid] = attn_b[tid];
    __syncthreads();
    float gamma = expf(p_s[4]);
    filterbank_block(p_s, F_s, sF_s, inv_s);
    do_glimpse(b, x, F_s, sF_s, gamma, xce, tmp_s, xs_s);
}

// ---------- in-megakernel GEMM phase ----------
__device__ void gemm_phase512(SmemGemm& sm,
                              const float* __restrict__ X, int ldx,
                              const float* __restrict__ W, int ldw,
                              float* __restrict__ Yp, int ldy,
                              int m0, int n0, int kbeg, int kend)
{
    int tid = threadIdx.x;
    int warp = tid >> 5, lane = tid & 31;
    int w4 = warp * 4;
    ull acc0[4] = {0ull, 0ull, 0ull, 0ull};
    ull acc1[4] = {0ull, 0ull, 0ull, 0ull};
    int ntile = (kend - kbeg + 15) >> 4;
    float ar[2], br[4];
    auto LDGT = [&](int k0) {
#pragma unroll
        for (int it = 0; it < 2; it++) {
            int idx = tid + it * 512;
            int m = idx >> 4, k = idx & 15;
            int gk = k0 + k;
            ar[it] = (gk < kend) ? X[(size_t)(m0 + m) * ldx + gk] : 0.f;
        }
#pragma unroll
        for (int it = 0; it < 4; it++) {
            int idx = tid + it * 512;
            int n = idx >> 4, k = idx & 15;
            int gk = k0 + k;
            br[it] = (gk < kend) ? W[(size_t)(n0 + n) * ldw + gk] : 0.f;
        }
    };
    auto STST = [&](int buf) {
#pragma unroll
        for (int it = 0; it < 2; it++) {
            int idx = tid + it * 512;
            sm.As2[buf][idx & 15][idx >> 4] = pk2(ar[it], ar[it]);
        }
#pragma unroll
        for (int it = 0; it < 4; it++) {
            int idx = tid + it * 512;
            sm.Bs[buf][idx & 15][idx >> 4] = br[it];
        }
    };
    LDGT(kbeg); STST(0); __syncthreads();
    for (int ti = 0; ti < ntile; ti++) {
        if (ti + 1 < ntile) LDGT(kbeg + (ti + 1) * 16);
        int buf = ti & 1;
#pragma unroll
        for (int kk = 0; kk < 16; kk++) {
            ull b0 = *reinterpret_cast<const ull*>(&sm.Bs[buf][kk][2 * lane]);
            ull b1 = *reinterpret_cast<const ull*>(&sm.Bs[buf][kk][2 * lane + 64]);
#pragma unroll
            for (int i = 0; i < 4; i++) {
                ull a = sm.As2[buf][kk][w4 + i];
                acc0[i] = fma2(a, b0, acc0[i]);
                acc1[i] = fma2(a, b1, acc1[i]);
            }
        }
        __syncthreads();
        if (ti + 1 < ntile) { STST(buf ^ 1); __syncthreads(); }
    }
#pragma unroll
    for (int i = 0; i < 4; i++) {
        int gm = m0 + w4 + i;
        int gn = n0 + 2 * lane;
        float lo, hi;
        upk2(acc0[i], lo, hi);
        *reinterpret_cast<float2*>(&Yp[(size_t)gm * ldy + gn]) = make_float2(lo, hi);
        upk2(acc1[i], lo, hi);
        *reinterpret_cast<float2*>(&Yp[(size_t)gm * ldy + gn + 64]) = make_float2(lo, hi);
    }
}

// ---------- enc fused phase (R10 shape: one block = one batch, everything) ----------
__device__ void enc_phase(SmemFused& sf, int b, const float* __restrict__ G,
                          float* __restrict__ cenc, float* __restrict__ xce,
                          float* __restrict__ xcd, const float* __restrict__ benc,
                          const float* __restrict__ mu_W, const float* __restrict__ mu_b,
                          const float* __restrict__ sig_W, const float* __restrict__ sig_b,
                          const float* __restrict__ eps_t, const float* __restrict__ apre,
                          const float* __restrict__ w2, const float* __restrict__ hlang)
{
    int tid = threadIdx.x, lane = tid & 31, warp = tid >> 5;
    const float* g0 = G + (size_t)b * NENC;
    {
        int u = tid;
        float gi = benc[u], gf = benc[512 + u], gg = benc[1024 + u], go = benc[1536 + u];
        float hp = 0.f;
#pragma unroll
        for (int z = 0; z < 3; z++) {
            const float* gz = g0 + (size_t)z * GPART;
            gi += gz[u]; gf += gz[512 + u]; gg += gz[1024 + u]; go += gz[1536 + u];
            hp += gz[2048 + u];
        }
        float c2 = sigm(gf) * cenc[b * 512 + u] + sigm(gi) * tanhf(gg);
        float h = sigm(go) * tanhf(c2);
        cenc[b * 512 + u] = c2;
        xce[(size_t)b * KENC + 662 + u] = h;
        sf.h_s[u] = h;
        sf.hd_s[u] = hp;
    }
    __syncthreads();
    for (int o = warp; o < 100; o += 16) {
        float sm = 0.f, ss = 0.f;
        const float* mr = mu_W + o * 512;
        const float* sr = sig_W + o * 512;
        for (int k = lane; k < 512; k += 32) {
            float hv = sf.h_s[k];
            sm += mr[k] * hv;
            ss += sr[k] * hv;
        }
#pragma unroll
        for (int off = 16; off; off >>= 1) {
            sm += __shfl_xor_sync(0xffffffffu, sm, off);
            ss += __shfl_xor_sync(0xffffffffu, ss, off);
        }
        if (!lane) {
            float mu = sm + mu_b[o];
            float sg = ss + sig_b[o];
            xcd[(size_t)b * KDEC + o] = mu + eps_t[b * 100 + o] * expf(sg);
        }
    }
    for (int t = warp; t < 32; t += 16) {
        const float* ap = apre + ((size_t)b * 32 + t) * 512;
        float s = 0.f;
        for (int al = lane; al < 512; al += 32)
            s += tanhf(ap[al] + sf.hd_s[al]) * w2[al];
#pragma unroll
        for (int o = 16; o; o >>= 1) s += __shfl_xor_sync(0xffffffffu, s, o);
        if (!lane) sf.lg_s[t] = s;
    }
    __syncthreads();
    if (warp == 0) {
        float v = sf.lg_s[lane];
        float m = v;
#pragma unroll
        for (int o = 16; o; o >>= 1) m = fmaxf(m, __shfl_xor_sync(0xffffffffu, m, o));
        float e = expf(v - m);
        float s = e;
#pragma unroll
        for (int o = 16; o; o >>= 1) s += __shfl_xor_sync(0xffffffffu, s, o);
        sf.lg_s[lane] = e / s;
    }
    __syncthreads();
    if (tid < 256) {
        int jj = tid;
        float s = 0.f;
        const float* hl = hlang + (size_t)b * 8192 + jj;
#pragma unroll 8
        for (int t = 0; t < 32; t++) s += sf.lg_s[t] * hl[t * 256];
        xcd[(size_t)b * KDEC + 100 + jj] = s;
    }
}

// ---------- dec fused phase (+ float4 output + next glimpse) ----------
__device__ void dec_phase(SmemFused& sf, int b, const float* __restrict__ G,
                          float* __restrict__ cdec, float* __restrict__ xce,
                          float* __restrict__ xcd, const float* __restrict__ x,
                          const float* __restrict__ bdec,
                          const float* __restrict__ write_W, const float* __restrict__ write_b,
                          const float* __restrict__ attn_W, const float* __restrict__ attn_b,
                          float* __restrict__ out_t, int doGlimpse)
{
    int tid = threadIdx.x, lane = tid & 31, warp = tid >> 5;
    const float* g0 = G + (size_t)b * 2048;
    {
        int u = tid;
        float gi = bdec[u], gf = bdec[512 + u], gg = bdec[1024 + u], go = bdec[1536 + u];
#pragma unroll
        for (int z = 0; z < 4; z++) {
            const float* gz = g0 + (size_t)z * GPART;
            gi += gz[u]; gf += gz[512 + u]; gg += gz[1024 + u]; go += gz[1536 + u];
        }
        float c2 = sigm(gf) * cdec[b * 512 + u] + sigm(gi) * tanhf(gg);
        float h = sigm(go) * tanhf(c2);
        cdec[b * 512 + u] = c2;
        xce[(size_t)b * KENC + 150 + u] = h;
        xcd[(size_t)b * KDEC + 356 + u] = h;
        sf.h_s[u] = h;
    }
    __syncthreads();
    for (int o = warp; o < 80; o += 16) {
        const float* row = (o < 75) ? (write_W + o * 512) : (attn_W + (o - 75) * 512);
        float s = 0.f;
        for (int k = lane; k < 512; k += 32) s += row[k] * sf.h_s[k];
#pragma unroll
        for (int off = 16; off; off >>= 1) s += __shfl_xor_sync(0xffffffffu, s, off);
        if (!lane) {
            if (o < 75) sf.w_s[o] = s + write_b[o];
            else sf.p_s[o - 75] = s + attn_b[o - 75];
        }
    }
    __syncthreads();
    float gamma = expf(sf.p_s[4]);
    float ginv = expf(-sf.p_s[4]);
    filterbank_block(sf.p_s, sf.F_s, sf.sF_s, sf.inv_s);
    for (int idx = tid; idx < 960; idx += 512) {
        int xx = idx & 63, rest = idx >> 6;
        int i5 = rest % 5, c = rest / 5;
        float s = 0.f;
#pragma unroll
        for (int jj = 0; jj < 5; jj++) s += sf.w_s[c * 25 + i5 * 5 + jj] * sf.F_s[0][jj][xx];
        sf.Mw_s[idx] = s;
    }
    __syncthreads();
    for (int idx4 = tid; idx4 < 3072; idx4 += 512) {
        int xg = (idx4 & 15) * 4;
        int yy = (idx4 >> 4) & 63;
        int c = idx4 >> 10;
        float4 s = make_float4(0.f, 0.f, 0.f, 0.f);
#pragma unroll
        for (int i = 0; i < 5; i++) {
            float f = sf.F_s[1][i][yy];
            const float4 m4 = *reinterpret_cast<const float4*>(&sf.Mw_s[(c * 5 + i) * 64 + xg]);
            s.x += f * m4.x; s.y += f * m4.y; s.z += f * m4.z; s.w += f * m4.w;
        }
        s.x *= ginv; s.y *= ginv; s.z *= ginv; s.w *= ginv;
        *reinterpret_cast<float4*>(&out_t[(size_t)b * 12288 + idx4 * 4]) = s;
    }
    if (doGlimpse)
        do_glimpse(b, x, sf.F_s, sf.sF_s, gamma, xce, sf.tmp_s, sf.xs_s);
}

// ---------- persistent scan megakernel ----------
__global__ __launch_bounds__(512) void k_scan(float* __restrict__ S,
                                              const float* __restrict__ x,
                                              const float* __restrict__ eps_q,
                                              const float* __restrict__ mu_W,
                                              const float* __restrict__ mu_b,
                                              const float* __restrict__ sig_W,
                                              const float* __restrict__ sig_b,
                                              const float* __restrict__ write_W,
                                              const float* __restrict__ write_b,
                                              const float* __restrict__ attn_W,
                                              const float* __restrict__ attn_b,
                                              const float* __restrict__ w2,
                                              float* __restrict__ out)
{
    __shared__ __align__(16) SmemAll sm;
    SmemGemm& sg = sm.g;
    SmemFused& sf = sm.f;
    int blk = blockIdx.x;
    float* xce = S + OFF_XCE;
    float* xcd = S + OFF_XCD;
    float* G   = S + OFF_G;

    for (int t = 0; t < 32; t++) {
        // --- P1: enc GEMM, 120 units ---
        if (blk < 120) {
            int z = blk / 40, rem = blk % 40;
            int my = rem / 20, nx = rem % 20;
            int kbeg = z * 400, kend = min(KENC, kbeg + 400);
            gemm_phase512(sg, xce, KENC, S + OFF_WENC2, KENC,
                          G + (size_t)z * GPART, NENC,
                          my * 64, nx * 128, kbeg, kend);
        }
        gsync();
        // --- P2: enc fused (one block = one batch) ---
        enc_phase(sf, blk, G, S + OFF_CENC, xce, xcd, S + OFF_BENC,
                  mu_W, mu_b, sig_W, sig_b,
                  eps_q + (size_t)t * 12800, S + OFF_APRE, w2, S + OFF_HLANG);
        gsync();
        // --- P3: dec GEMM, 128 units ---
        {
            int z = blk >> 5, rem = blk & 31;
            int my = rem >> 4, nx = rem & 15;
            int kbeg = z * 224, kend = min(KDEC, kbeg + 224);
            gemm_phase512(sg, xcd, KDEC, S + OFF_WDEC, KDEC,
                          G + (size_t)z * GPART, 2048,
                          my * 64, nx * 128, kbeg, kend);
        }
        gsync();
        // --- P4: dec fused + output + next glimpse ---
        dec_phase(sf, blk, G, S + OFF_CDEC, xce, xcd, x, S + OFF_BDEC,
                  write_W, write_b, attn_W, attn_b,
                  out + (size_t)t * 1572864u, (t < 31) ? 1 : 0);
        if (t < 31) gsync();
    }
}

// ---------- host ----------
extern "C" void kernel_launch(void* const* d_in, const int* in_sizes, int n_in,
                              void* d_out, int out_size)
{
    const float* x       = (const float*)d_in[0];
    const float* y       = (const float*)d_in[1];
    const float* eps_q   = (const float*)d_in[2];
    const float* enc_Wih = (const float*)d_in[3];
    const float* enc_Whh = (const float*)d_in[4];
    const float* enc_bih = (const float*)d_in[5];
    const float* enc_bhh = (const float*)d_in[6];
    const float* dec_Wih = (const float*)d_in[7];
    const float* dec_Whh = (const float*)d_in[8];
    const float* dec_bih = (const float*)d_in[9];
    const float* dec_bhh = (const float*)d_in[10];
    const float* mu_W    = (const float*)d_in[11];
    const float* mu_b    = (const float*)d_in[12];
    const float* sig_W   = (const float*)d_in[13];
    const float* sig_b   = (const float*)d_in[14];
    const float* write_W = (const float*)d_in[15];
    const float* write_b = (const float*)d_in[16];
    const float* align_W1= (const float*)d_in[17];
    const float* align_b1= (const float*)d_in[18];
    const float* align_w2= (const float*)d_in[19];
    const float* attn_W  = (const float*)d_in[20];
    const float* attn_b  = (const float*)d_in[21];
    const float* lf_Wih  = (const float*)d_in[22];
    const float* lf_Whh  = (const float*)d_in[23];
    const float* lf_bih  = (const float*)d_in[24];
    const float* lf_bhh  = (const float*)d_in[25];
    const float* lb_Wih  = (const float*)d_in[26];
    const float* lb_Whh  = (const float*)d_in[27];
    const float* lb_bih  = (const float*)d_in[28];
    const float* lb_bhh  = (const float*)d_in[29];
    float* out = (float*)d_out;

    float* S;
    cudaGetSymbolAddress((void**)&S, S_g);

    cudaFuncSetAttribute(k_bilstm_smem,
                         cudaFuncAttributeMaxDynamicSharedMemorySize, BILSTM_SMEM);

    k_init<<<4096, 256>>>(S, enc_Wih, enc_Whh, enc_bih, enc_bhh,
                          dec_Wih, dec_Whh, dec_bih, dec_bhh,
                          align_W1, lf_Whh, lb_Whh,
                          lf_bih, lf_bhh, lb_bih, lb_bhh);

    gemm2b<<<dim3(4, 64), 256>>>(y, 300, lf_Wih, 300, S + OFF_BLF,
                                 S + OFF_LPRE, 512, 300);
    gemm2b<<<dim3(4, 64), 256>>>(y, 300, lb_Wih, 300, S + OFF_BLB,
                                 S + OFF_LPRE + 2097152u, 512, 300);

    k_bilstm_smem<<<128, 512, BILSTM_SMEM>>>(S + OFF_LPRE, S + OFF_WHT, S + OFF_HLANG);

    gemm2b<<<dim3(4, 64), 256>>>(S + OFF_HLANG, 256, align_W1 + 512, 768,
                                 align_b1, S + OFF_APRE, 512, 256);

    k_glimpse0<<<128, 512>>>(S + OFF_XCE, x, attn_b);

    k_scan<<<NB, 512>>>(S, x, eps_q, mu_W, mu_b, sig_W, sig_b,
                        write_W, write_b, attn_W, attn_b, align_w2, out);
}